// round 13
// baseline (speedup 1.0000x reference)
#include <cuda_runtime.h>
#include <cuda_fp16.h>
#include <cstdint>
#include <math.h>

// Problem constants
#define NIMG 32
#define LSEQ 196
#define KEEP 98
#define SEQ  99
#define DMODEL 1024
#define NHEAD 16
#define DHEAD 64
#define DMLP 4096
#define NLAYER 6
#define PDIM 768
#define NTOK (NIMG*SEQ)  // 3168
#define NPAT (NIMG*LSEQ) // 6272
#define QKVN (3*DMODEL)  // 3072
#define NSLOT 13

// ======================= scratch (device globals) =======================
__device__ __half g_patches[(size_t)NPAT*PDIM];
__device__ float  g_x0[(size_t)NPAT*DMODEL];
__device__ float  g_x [(size_t)NTOK*DMODEL];
__device__ __half g_y [(size_t)NTOK*DMODEL];
__device__ __half g_qkv[(size_t)NTOK*QKVN];
__device__ __half g_ao[(size_t)NTOK*DMODEL];
__device__ __half g_h1[(size_t)NTOK*DMLP];
__device__ int    g_keep[NIMG*KEEP];
__device__ float  g_sum[(size_t)NSLOT*NTOK];
__device__ float  g_ssq[(size_t)NSLOT*NTOK];
// transposed half weights (K-major, [N,K])
__device__ __half g_pwt[(size_t)DMODEL*PDIM];
__device__ __half g_wqkvt[(size_t)NLAYER*QKVN*DMODEL];
__device__ __half g_wot[(size_t)NLAYER*DMODEL*DMODEL];
__device__ __half g_w1t[(size_t)NLAYER*DMLP*DMODEL];
__device__ __half g_w2t[(size_t)NLAYER*DMODEL*DMLP];
__device__ float  g_bqkv[(size_t)NLAYER*QKVN];

// ======================= helpers =======================
__device__ __forceinline__ uint32_t smem_u32(const void* p) {
    uint32_t a;
    asm("{ .reg .u64 t; cvta.to.shared.u64 t, %1; cvt.u32.u64 %0, t; }" : "=r"(a) : "l"(p));
    return a;
}
__device__ __forceinline__ void cp_async16(uint32_t dst, const void* src, bool ok) {
    asm volatile("cp.async.ca.shared.global [%0], [%1], 16, %2;"
                 :: "r"(dst), "l"(src), "r"(ok ? 16 : 0) : "memory");
}
#define CP_COMMIT() asm volatile("cp.async.commit_group;" ::: "memory")
#define CP_WAIT(n)  asm volatile("cp.async.wait_group %0;" :: "n"(n) : "memory")

__device__ __forceinline__ void ldmx4(uint32_t r[4], uint32_t addr) {
    asm volatile("ldmatrix.sync.aligned.m8n8.x4.shared.b16 {%0,%1,%2,%3}, [%4];"
                 : "=r"(r[0]), "=r"(r[1]), "=r"(r[2]), "=r"(r[3]) : "r"(addr));
}
__device__ __forceinline__ void mma_f16(float c[4], const uint32_t a[4],
                                        uint32_t b0, uint32_t b1) {
    asm volatile(
        "mma.sync.aligned.m16n8k16.row.col.f32.f16.f16.f32 "
        "{%0,%1,%2,%3}, {%4,%5,%6,%7}, {%8,%9}, {%0,%1,%2,%3};\n"
        : "+f"(c[0]), "+f"(c[1]), "+f"(c[2]), "+f"(c[3])
        : "r"(a[0]), "r"(a[1]), "r"(a[2]), "r"(a[3]), "r"(b0), "r"(b1));
}
__device__ __forceinline__ float gelu_f(float x) {
    float x3 = x * x * x;
    return 0.5f * x * (1.0f + tanhf(0.7978845608028654f * (x + 0.044715f * x3)));
}

// ======================= templated fp16 mma.sync GEMM =======================
// WM x WN warp grid; CTA tile (WM*32) x 128; THREADS = WM*WN*32.
// 256-thr/64-row config runs 3 CTAs/SM; 512-thr/128-row runs 2 CTAs/SM.
#define BKH 64
#define NSTAGE 3

template <int WM, int WN, int NT2, int THREADS>
__global__ void __launch_bounds__(THREADS, (THREADS == 256 && WM == 2 ? 3 : 2))
gemm_h(const __half* __restrict__ A, const __half* __restrict__ Bt,
       const float* __restrict__ bias, const float* __restrict__ res,
       float* __restrict__ Cf, __half* __restrict__ Ch,
       int M, int N, int K, int act,
       float* __restrict__ sumOut, float* __restrict__ ssqOut) {
    constexpr int BM_ = WM * 32;
    constexpr int A_TILE = BM_ * 128;
    constexpr int STAGE = A_TILE + 16384;
    constexpr int TOT_ROWS = BM_ + 128;

    extern __shared__ char smem[];
    int tid = threadIdx.x;
    int wid = tid >> 5, lane = tid & 31;
    int g = lane >> 2, tg = lane & 3;
    int warp_m = wid % WM, warp_n = wid / WM;
    int m0 = blockIdx.y * BM_, n0 = blockIdx.x * 128;

    uint32_t sbase = smem_u32(smem);

    float acc[2][2 * NT2][4];
#pragma unroll
    for (int i = 0; i < 2; i++)
#pragma unroll
        for (int j = 0; j < 2 * NT2; j++)
#pragma unroll
            for (int l = 0; l < 4; l++) acc[i][j][l] = 0.f;

    auto load_stage = [&](int c) {
        int slot = c % NSTAGE;
        int k0 = c * BKH;
        uint32_t base = sbase + slot * STAGE;
#pragma unroll
        for (int u = tid; u < TOT_ROWS * 8; u += THREADS) {
            int row = u >> 3, q = u & 7;
            uint32_t off = (uint32_t)((q ^ (row & 7)) * 16);
            if (row < BM_) {
                bool ok = (m0 + row) < M;
                cp_async16(base + row * 128 + off,
                           A + (size_t)(m0 + row) * K + k0 + q * 8, ok);
            } else {
                int r2 = row - BM_;
                bool ok = (n0 + r2) < N;
                cp_async16(base + A_TILE + r2 * 128 + off,
                           Bt + (size_t)(n0 + r2) * K + k0 + q * 8, ok);
            }
        }
        CP_COMMIT();
    };

    const int NC = K / BKH;
    load_stage(0);
    load_stage(1);

    int rA = warp_m * 32 + ((lane >> 3) & 1) * 8 + (lane & 7);
    int kAh = (lane >> 4) & 1;
    int rB = warp_n * (NT2 * 16) + ((lane >> 4) & 1) * 8 + (lane & 7);
    int kBh = (lane >> 3) & 1;

    for (int c = 0; c < NC; c++) {
        if (c == NC - 1) { CP_WAIT(0); } else { CP_WAIT(1); }
        __syncthreads();
        if (c + 2 < NC) load_stage(c + 2);

        int slot = c % NSTAGE;
        uint32_t aBase = sbase + slot * STAGE;
        uint32_t bBase = aBase + A_TILE;

#pragma unroll
        for (int ks = 0; ks < 4; ks++) {
            uint32_t a[2][4];
#pragma unroll
            for (int mt = 0; mt < 2; mt++) {
                int row = rA + mt * 16;
                ldmx4(a[mt], aBase + row * 128 +
                      (uint32_t)(((2 * ks + kAh) ^ (row & 7)) * 16));
            }
            uint32_t b[NT2][4];
#pragma unroll
            for (int nt2 = 0; nt2 < NT2; nt2++) {
                int row = rB + nt2 * 16;
                ldmx4(b[nt2], bBase + row * 128 +
                      (uint32_t)(((2 * ks + kBh) ^ (row & 7)) * 16));
            }
#pragma unroll
            for (int mt = 0; mt < 2; mt++)
#pragma unroll
                for (int nt2 = 0; nt2 < NT2; nt2++) {
                    mma_f16(acc[mt][2 * nt2 + 0], a[mt], b[nt2][0], b[nt2][1]);
                    mma_f16(acc[mt][2 * nt2 + 1], a[mt], b[nt2][2], b[nt2][3]);
                }
        }
    }

    // epilogue (+ optional per-row stats)
#pragma unroll
    for (int mt = 0; mt < 2; mt++) {
#pragma unroll
        for (int hh = 0; hh < 2; hh++) {
            int row = m0 + warp_m * 32 + mt * 16 + g + hh * 8;
            bool rok = row < M;
            const float* rrow = (rok && res) ? res + (size_t)row * N : nullptr;
            float ps_ = 0.f, qs_ = 0.f;
#pragma unroll
            for (int j = 0; j < 2 * NT2; j++) {
                if (!rok) continue;
                int col = n0 + warp_n * (NT2 * 16) + (j >> 1) * 16 + (j & 1) * 8 + 2 * tg;
                float v0 = acc[mt][j][hh * 2 + 0] + bias[col];
                float v1 = acc[mt][j][hh * 2 + 1] + bias[col + 1];
                if (act == 1) { v0 = gelu_f(v0); v1 = gelu_f(v1); }
                if (rrow) { v0 += rrow[col]; v1 += rrow[col + 1]; }
                if (Ch) {
                    *(__half2*)(Ch + (size_t)row * N + col) = __floats2half2_rn(v0, v1);
                } else {
                    float2 o; o.x = v0; o.y = v1;
                    *(float2*)(Cf + (size_t)row * N + col) = o;
                }
                ps_ += v0 + v1;
                qs_ += v0 * v0 + v1 * v1;
            }
            if (sumOut) {
                ps_ += __shfl_xor_sync(0xffffffffu, ps_, 1);
                qs_ += __shfl_xor_sync(0xffffffffu, qs_, 1);
                ps_ += __shfl_xor_sync(0xffffffffu, ps_, 2);
                qs_ += __shfl_xor_sync(0xffffffffu, qs_, 2);
                if (rok && tg == 0) {
                    atomicAdd(&sumOut[row], ps_);
                    atomicAdd(&ssqOut[row], qs_);
                }
            }
        }
    }
}

#define SMEM_A (NSTAGE * (128 * 128 + 16384))  // 98304 (128-row tile)
#define SMEM_B (NSTAGE * (64 * 128 + 16384))   // 73728 (64-row tile)

// ======================= unified weight prep (64x64 float4 tiles) ==========
#define TPW  192
#define TSQ  256
#define TW1  1024
#define Z_PW   0
#define Z_WQ   (Z_PW + TPW)
#define Z_WK   (Z_WQ + NLAYER*TSQ)
#define Z_WV   (Z_WK + NLAYER*TSQ)
#define Z_WO   (Z_WV + NLAYER*TSQ)
#define Z_W1   (Z_WO + NLAYER*TSQ)
#define Z_W2   (Z_W1 + NLAYER*TW1)
#define Z_BIAS (Z_W2 + NLAYER*TW1)
#define Z_TOT  (Z_BIAS + 72)

__global__ void __launch_bounds__(256)
wprep_kernel(const float* __restrict__ pw,
             const float* __restrict__ wq, const float* __restrict__ wk,
             const float* __restrict__ wv, const float* __restrict__ wo,
             const float* __restrict__ w1, const float* __restrict__ w2,
             const float* __restrict__ bq, const float* __restrict__ bk,
             const float* __restrict__ bv,
             __half* __restrict__ pwt, __half* __restrict__ wqkvt,
             __half* __restrict__ wot, __half* __restrict__ w1t,
             __half* __restrict__ w2t, float* __restrict__ bqkv) {
    __shared__ float t[64][65];
    int z = blockIdx.x;
    int tid = threadIdx.x;
    const size_t DD = (size_t)DMODEL * DMODEL;
    const size_t DM = (size_t)DMODEL * DMLP;

    auto tr = [&](const float* ip, __half* op, int R, int C, int tx, int ty) {
        int c0 = tx * 64, r0 = ty * 64;
#pragma unroll
        for (int it = 0; it < 4; it++) {
            int idx = it * 256 + tid;
            int r = idx >> 4, c4 = (idx & 15) * 4;
            float4 v = *(const float4*)(ip + (size_t)(r0 + r) * C + c0 + c4);
            t[r][c4 + 0] = v.x; t[r][c4 + 1] = v.y;
            t[r][c4 + 2] = v.z; t[r][c4 + 3] = v.w;
        }
        __syncthreads();
#pragma unroll
        for (int it = 0; it < 4; it++) {
            int idx = it * 256 + tid;
            int oc = idx >> 4, r4 = (idx & 15) * 4;
            __half2 h0 = __floats2half2_rn(t[r4 + 0][oc], t[r4 + 1][oc]);
            __half2 h1 = __floats2half2_rn(t[r4 + 2][oc], t[r4 + 3][oc]);
            uint2 pk; pk.x = *(uint32_t*)&h0; pk.y = *(uint32_t*)&h1;
            *(uint2*)(op + (size_t)(c0 + oc) * R + r0 + r4) = pk;
        }
    };

    if (z < Z_WQ) {
        int r = z - Z_PW;
        tr(pw, pwt, PDIM, DMODEL, r % 16, r / 16);
    } else if (z < Z_WK) {
        int r = z - Z_WQ; int l = r / TSQ; r %= TSQ;
        tr(wq + l * DD, wqkvt + l * 3 * DD, DMODEL, DMODEL, r % 16, r / 16);
    } else if (z < Z_WV) {
        int r = z - Z_WK; int l = r / TSQ; r %= TSQ;
        tr(wk + l * DD, wqkvt + l * 3 * DD + DD, DMODEL, DMODEL, r % 16, r / 16);
    } else if (z < Z_WO) {
        int r = z - Z_WV; int l = r / TSQ; r %= TSQ;
        tr(wv + l * DD, wqkvt + l * 3 * DD + 2 * DD, DMODEL, DMODEL, r % 16, r / 16);
    } else if (z < Z_W1) {
        int r = z - Z_WO; int l = r / TSQ; r %= TSQ;
        tr(wo + l * DD, wot + l * DD, DMODEL, DMODEL, r % 16, r / 16);
    } else if (z < Z_W2) {
        int r = z - Z_W1; int l = r / TW1; r %= TW1;
        tr(w1 + l * DM, w1t + l * DM, DMODEL, DMLP, r % 64, r / 64);
    } else if (z < Z_BIAS) {
        int r = z - Z_W2; int l = r / TW1; r %= TW1;
        tr(w2 + l * DM, w2t + l * DM, DMLP, DMODEL, r % 16, r / 16);
    } else {
        int idx = (z - Z_BIAS) * 256 + tid;
        if (idx < NLAYER * QKVN) {
            int l = idx / QKVN, j = idx % QKVN;
            float v;
            if (j < DMODEL) v = bq[l * DMODEL + j];
            else if (j < 2 * DMODEL) v = bk[l * DMODEL + j - DMODEL];
            else v = bv[l * DMODEL + j - 2 * DMODEL];
            bqkv[idx] = v;
        }
    }
}

// ======================= patchify =======================
__global__ void patchify_kernel(const float* __restrict__ imgs, __half* __restrict__ out) {
    int idx = blockIdx.x * blockDim.x + threadIdx.x;
    if (idx >= NPAT * PDIM) return;
    int j = idx % PDIM;
    int l = (idx / PDIM) % LSEQ;
    int n = idx / (PDIM * LSEQ);
    int c  = j % 3;
    int px = (j / 3) % 16;
    int py = j / 48;
    int pw = l % 14;
    int ph = l / 14;
    out[idx] = __float2half_rn(imgs[(((size_t)n * 224 + ph * 16 + py) * 224 + pw * 16 + px) * 3 + c]);
}

// ======================= ranking / mask =======================
__global__ void rank_kernel(const float* __restrict__ noise, int* __restrict__ keep,
                            float* __restrict__ mask_out) {
    int n = blockIdx.x;
    __shared__ float ns[LSEQ];
    int i = threadIdx.x;
    if (i < LSEQ) ns[i] = noise[n * LSEQ + i];
    __syncthreads();
    if (i < LSEQ) {
        float my = ns[i];
        int r = 0;
        for (int j = 0; j < LSEQ; j++) {
            float vj = ns[j];
            r += (vj < my) || (vj == my && j < i);
        }
        if (r < KEEP) keep[n * KEEP + r] = i;
        mask_out[n * LSEQ + i] = (r < KEEP) ? 0.0f : 1.0f;
    }
}

// ======================= zero stats =======================
__global__ void zero2_kernel(float* __restrict__ a, float* __restrict__ b) {
    int i = blockIdx.x * 256 + threadIdx.x;
    if (i < NSLOT * NTOK) { a[i] = 0.f; b[i] = 0.f; }
}

// ======================= gather + cls + pos (+stats slot0) =======================
__global__ void gather_kernel(const float* __restrict__ x0, const float* __restrict__ pos,
                              const float* __restrict__ cls, const int* __restrict__ keep,
                              float* __restrict__ x, float* __restrict__ sum0,
                              float* __restrict__ ssq0) {
    int b = blockIdx.x;
    int n = b / SEQ, s = b % SEQ;
    float* xo = x + (size_t)b * DMODEL;
    int tid = threadIdx.x;
    float ls = 0.f, lq = 0.f;
    if (s == 0) {
        for (int d = tid; d < DMODEL; d += 256) {
            float v = cls[d]; xo[d] = v; ls += v; lq += v * v;
        }
    } else {
        int id = keep[n * KEEP + s - 1];
        const float* src = x0 + ((size_t)n * LSEQ + id) * DMODEL;
        const float* pp  = pos + (size_t)id * DMODEL;
        for (int d = tid; d < DMODEL; d += 256) {
            float v = src[d] + pp[d]; xo[d] = v; ls += v; lq += v * v;
        }
    }
    __shared__ float rs[256], rq[256];
    rs[tid] = ls; rq[tid] = lq; __syncthreads();
    for (int o = 128; o > 0; o >>= 1) {
        if (tid < o) { rs[tid] += rs[tid + o]; rq[tid] += rq[tid + o]; }
        __syncthreads();
    }
    if (tid == 0) { sum0[b] = rs[0]; ssq0[b] = rq[0]; }
}

// ======================= LN apply (stats precomputed) =======================
__global__ void ln_apply(const float* __restrict__ x, const float* __restrict__ s,
                         const float* __restrict__ b, const float* __restrict__ sum,
                         const float* __restrict__ ssq, float* __restrict__ yf,
                         __half* __restrict__ yh) {
    int row = blockIdx.x;
    int d = threadIdx.x * 8;
    float m = sum[row] * (1.0f / DMODEL);
    float var = ssq[row] * (1.0f / DMODEL) - m * m;
    float rstd = rsqrtf(var + 1e-6f);
    const float* xr = x + (size_t)row * DMODEL + d;
    float4 u0 = *(const float4*)(xr);
    float4 u1 = *(const float4*)(xr + 4);
    float4 s0 = *(const float4*)(s + d);
    float4 s1 = *(const float4*)(s + d + 4);
    float4 b0 = *(const float4*)(b + d);
    float4 b1 = *(const float4*)(b + d + 4);
    float v[8];
    v[0] = (u0.x - m) * rstd * s0.x + b0.x;
    v[1] = (u0.y - m) * rstd * s0.y + b0.y;
    v[2] = (u0.z - m) * rstd * s0.z + b0.z;
    v[3] = (u0.w - m) * rstd * s0.w + b0.w;
    v[4] = (u1.x - m) * rstd * s1.x + b1.x;
    v[5] = (u1.y - m) * rstd * s1.y + b1.y;
    v[6] = (u1.z - m) * rstd * s1.z + b1.z;
    v[7] = (u1.w - m) * rstd * s1.w + b1.w;
    if (yh) {
        __half2 hh[4];
        hh[0] = __floats2half2_rn(v[0], v[1]);
        hh[1] = __floats2half2_rn(v[2], v[3]);
        hh[2] = __floats2half2_rn(v[4], v[5]);
        hh[3] = __floats2half2_rn(v[6], v[7]);
        *(uint4*)(yh + (size_t)row * DMODEL + d) = *(uint4*)hh;
    } else {
        *(float4*)(yf + (size_t)row * DMODEL + d) = make_float4(v[0], v[1], v[2], v[3]);
        *(float4*)(yf + (size_t)row * DMODEL + d + 4) = make_float4(v[4], v[5], v[6], v[7]);
    }
}

// ======================= attention (8 warps/block, fp32 math) ==========
__global__ void __launch_bounds__(256)
attn_kernel(const __half* __restrict__ qkv, __half* __restrict__ o) {
    int nh = blockIdx.x;
    int n = nh / NHEAD, h = nh % NHEAD;
    __shared__ float Ks[SEQ][DHEAD + 1];
    __shared__ __half2 Vs[SEQ][DHEAD / 2];
    __shared__ float ps[8][SEQ];
    __shared__ float qs[8][DHEAD];
    int tid = threadIdx.x;
    int w = tid >> 5, lane = tid & 31;

    const __half* qb = qkv + (size_t)n * SEQ * QKVN + h * DHEAD;
    const __half* kb = qb + DMODEL;
    const __half* vb = qb + 2 * DMODEL;
    __half* ob = o + (size_t)n * SEQ * DMODEL + h * DHEAD;

    for (int idx = tid; idx < SEQ * DHEAD; idx += 256) {
        int j = idx / DHEAD, d = idx % DHEAD;
        Ks[j][d] = __half2float(kb[(size_t)j * QKVN + d]);
    }
    for (int idx = tid; idx < SEQ * (DHEAD / 2); idx += 256) {
        int j = idx >> 5, d2 = idx & 31;
        Vs[j][d2] = *(const __half2*)(vb + (size_t)j * QKVN + 2 * d2);
    }
    __syncthreads();

    for (int si = w; si < SEQ; si += 8) {
        qs[w][lane]      = __half2float(qb[(size_t)si * QKVN + lane]);
        qs[w][lane + 32] = __half2float(qb[(size_t)si * QKVN + lane + 32]);
        __syncwarp();
        float sc[4];
#pragma unroll
        for (int m = 0; m < 4; m++) {
            int j = lane + m * 32;
            float a = 0.f;
            if (j < SEQ) {
#pragma unroll 8
                for (int d = 0; d < DHEAD; d++) a += qs[w][d] * Ks[j][d];
                sc[m] = a * 0.125f;
            } else sc[m] = -1e30f;
        }
        float mx = fmaxf(fmaxf(sc[0], sc[1]), fmaxf(sc[2], sc[3]));
#pragma unroll
        for (int off = 16; off > 0; off >>= 1) mx = fmaxf(mx, __shfl_xor_sync(0xffffffffu, mx, off));
        float sum = 0.f;
#pragma unroll
        for (int m = 0; m < 4; m++) {
            int j = lane + m * 32;
            float e = (j < SEQ) ? __expf(sc[m] - mx) : 0.f;
            sc[m] = e; sum += e;
        }
#pragma unroll
        for (int off = 16; off > 0; off >>= 1) sum += __shfl_xor_sync(0xffffffffu, sum, off);
        float inv = 1.0f / sum;
#pragma unroll
        for (int m = 0; m < 4; m++) {
            int j = lane + m * 32;
            if (j < SEQ) ps[w][j] = sc[m] * inv;
        }
        __syncwarp();
        float a0 = 0.f, a1 = 0.f;
        for (int j = 0; j < SEQ; j++) {
            float pv = ps[w][j];
            float2 vf = __half22float2(Vs[j][lane]);
            a0 += pv * vf.x;
            a1 += pv * vf.y;
        }
        *(__half2*)(ob + (size_t)si * DMODEL + 2 * lane) = __floats2half2_rn(a0, a1);
        __syncwarp();
    }
}

// ======================= launch =======================
extern "C" void kernel_launch(void* const* d_in, const int* in_sizes, int n_in,
                              void* d_out, int out_size) {
    const float* imgs    = (const float*)d_in[0];
    const float* noise   = (const float*)d_in[1];
    const float* patch_w = (const float*)d_in[2];
    const float* patch_b = (const float*)d_in[3];
    const float* pos_emb = (const float*)d_in[4];
    const float* cls_tok = (const float*)d_in[5];
    const float* ln1_s   = (const float*)d_in[6];
    const float* ln1_b   = (const float*)d_in[7];
    const float* wq      = (const float*)d_in[8];
    const float* bq      = (const float*)d_in[9];
    const float* wk      = (const float*)d_in[10];
    const float* bk      = (const float*)d_in[11];
    const float* wv      = (const float*)d_in[12];
    const float* bv      = (const float*)d_in[13];
    const float* wo      = (const float*)d_in[14];
    const float* bo      = (const float*)d_in[15];
    const float* ln2_s   = (const float*)d_in[16];
    const float* ln2_b   = (const float*)d_in[17];
    const float* w1      = (const float*)d_in[18];
    const float* b1      = (const float*)d_in[19];
    const float* w2      = (const float*)d_in[20];
    const float* b2      = (const float*)d_in[21];
    const float* lnf_s   = (const float*)d_in[22];
    const float* lnf_b   = (const float*)d_in[23];

    float* out = (float*)d_out;
    float* out_mask = out + (size_t)NTOK * DMODEL;

    __half *patches, *y, *qkv, *ao, *h1, *pwt, *wqkvt, *wot, *w1t, *w2t;
    float *x0, *x, *bqkv, *gsum, *gssq;
    int* keep;
    cudaGetSymbolAddress((void**)&patches, g_patches);
    cudaGetSymbolAddress((void**)&x0, g_x0);
    cudaGetSymbolAddress((void**)&x,  g_x);
    cudaGetSymbolAddress((void**)&y,  g_y);
    cudaGetSymbolAddress((void**)&qkv, g_qkv);
    cudaGetSymbolAddress((void**)&ao, g_ao);
    cudaGetSymbolAddress((void**)&h1, g_h1);
    cudaGetSymbolAddress((void**)&keep, g_keep);
    cudaGetSymbolAddress((void**)&pwt, g_pwt);
    cudaGetSymbolAddress((void**)&wqkvt, g_wqkvt);
    cudaGetSymbolAddress((void**)&wot, g_wot);
    cudaGetSymbolAddress((void**)&w1t, g_w1t);
    cudaGetSymbolAddress((void**)&w2t, g_w2t);
    cudaGetSymbolAddress((void**)&bqkv, g_bqkv);
    cudaGetSymbolAddress((void**)&gsum, g_sum);
    cudaGetSymbolAddress((void**)&gssq, g_ssq);

    cudaFuncSetAttribute(gemm_h<4, 4, 2, 512>, cudaFuncAttributeMaxDynamicSharedMemorySize, SMEM_A);
    cudaFuncSetAttribute(gemm_h<2, 4, 2, 256>, cudaFuncAttributeMaxDynamicSharedMemorySize, SMEM_B);

    patchify_kernel<<<(NPAT * PDIM + 255) / 256, 256>>>(imgs, patches);
    rank_kernel<<<NIMG, 224>>>(noise, keep, out_mask);
    zero2_kernel<<<(NSLOT * NTOK + 255) / 256, 256>>>(gsum, gssq);
    wprep_kernel<<<Z_TOT, 256>>>(patch_w, wq, wk, wv, wo, w1, w2, bq, bk, bv,
                                 pwt, wqkvt, wot, w1t, w2t, bqkv);

    // patch embed: M=6272, N=1024 (128x128 tiles, 512 threads)
    {
        dim3 grid(DMODEL / 128, NPAT / 128);
        gemm_h<4, 4, 2, 512><<<grid, 512, SMEM_A>>>(patches, pwt, patch_b, nullptr, x0, nullptr,
                                                    NPAT, DMODEL, PDIM, 0, nullptr, nullptr);
    }
    gather_kernel<<<NTOK, 256>>>(x0, pos_emb, cls_tok, keep, x, gsum, gssq);

    dim3 gQKV(QKVN / 128, (NTOK + 127) / 128);    // 24 x 25 (128-tile, 512 thr)
    dim3 gD64(DMODEL / 128, (NTOK + 63) / 64);    // 8 x 50  (64-tile, 3 CTA/SM)
    dim3 gM(DMLP / 128, (NTOK + 127) / 128);      // 32 x 25 (128-tile, 512 thr)

    for (int i = 0; i < NLAYER; i++) {
        const __half* wqkv_i = wqkvt + (size_t)i * 3 * DMODEL * DMODEL;
        const __half* wo_i = wot + (size_t)i * DMODEL * DMODEL;
        const __half* w1_i = w1t + (size_t)i * DMODEL * DMLP;
        const __half* w2_i = w2t + (size_t)i * DMLP * DMODEL;
        float* s0 = gsum + (size_t)(2 * i) * NTOK;
        float* q0 = gssq + (size_t)(2 * i) * NTOK;
        float* s1 = gsum + (size_t)(2 * i + 1) * NTOK;
        float* q1 = gssq + (size_t)(2 * i + 1) * NTOK;
        float* s2 = gsum + (size_t)(2 * i + 2) * NTOK;
        float* q2 = gssq + (size_t)(2 * i + 2) * NTOK;

        ln_apply<<<NTOK, 128>>>(x, ln1_s + i * DMODEL, ln1_b + i * DMODEL, s0, q0, nullptr, y);
        gemm_h<4, 4, 2, 512><<<gQKV, 512, SMEM_A>>>(y, wqkv_i, bqkv + (size_t)i * QKVN, nullptr,
                                                    nullptr, qkv, NTOK, QKVN, DMODEL, 0,
                                                    nullptr, nullptr);
        attn_kernel<<<NIMG * NHEAD, 256>>>(qkv, ao);
        gemm_h<2, 4, 2, 256><<<gD64, 256, SMEM_B>>>(ao, wo_i, bo + i * DMODEL, x, x, nullptr,
                                                    NTOK, DMODEL, DMODEL, 0, s1, q1);
        ln_apply<<<NTOK, 128>>>(x, ln2_s + i * DMODEL, ln2_b + i * DMODEL, s1, q1, nullptr, y);
        gemm_h<4, 4, 2, 512><<<gM, 512, SMEM_A>>>(y, w1_i, b1 + i * DMLP, nullptr,
                                                  nullptr, h1, NTOK, DMLP, DMODEL, 1,
                                                  nullptr, nullptr);
        gemm_h<2, 4, 2, 256><<<gD64, 256, SMEM_B>>>(h1, w2_i, b2 + i * DMODEL, x, x, nullptr,
                                                    NTOK, DMODEL, DMLP, 0, s2, q2);
    }
    ln_apply<<<NTOK, 128>>>(x, lnf_s, lnf_b, gsum + (size_t)12 * NTOK,
                            gssq + (size_t)12 * NTOK, out, nullptr);
}

// round 14
// speedup vs baseline: 1.1367x; 1.1367x over previous
#include <cuda_runtime.h>
#include <cuda_fp16.h>
#include <cstdint>
#include <math.h>

// Problem constants
#define NIMG 32
#define LSEQ 196
#define KEEP 98
#define SEQ  99
#define DMODEL 1024
#define NHEAD 16
#define DHEAD 64
#define DMLP 4096
#define NLAYER 6
#define PDIM 768
#define NTOK (NIMG*SEQ)   // 3168
#define NKEPT (NIMG*KEEP) // 3136
#define QKVN (3*DMODEL)   // 3072
#define NSLOT 13

// ======================= scratch (device globals) =======================
__device__ __half g_patches[(size_t)NKEPT*PDIM];
__device__ float  g_x0[(size_t)NKEPT*DMODEL];
__device__ float  g_x [(size_t)NTOK*DMODEL];
__device__ __half g_y [(size_t)NTOK*DMODEL];
__device__ __half g_qkv[(size_t)NTOK*QKVN];
__device__ __half g_ao[(size_t)NTOK*DMODEL];
__device__ __half g_h1[(size_t)NTOK*DMLP];
__device__ int    g_keep[NIMG*KEEP];
__device__ float  g_sum[(size_t)NSLOT*NTOK];
__device__ float  g_ssq[(size_t)NSLOT*NTOK];
// transposed half weights (K-major, [N,K])
__device__ __half g_pwt[(size_t)DMODEL*PDIM];
__device__ __half g_wqkvt[(size_t)NLAYER*QKVN*DMODEL];
__device__ __half g_wot[(size_t)NLAYER*DMODEL*DMODEL];
__device__ __half g_w1t[(size_t)NLAYER*DMLP*DMODEL];
__device__ __half g_w2t[(size_t)NLAYER*DMODEL*DMLP];
__device__ float  g_bqkv[(size_t)NLAYER*QKVN];

// ======================= helpers =======================
__device__ __forceinline__ uint32_t smem_u32(const void* p) {
    uint32_t a;
    asm("{ .reg .u64 t; cvta.to.shared.u64 t, %1; cvt.u32.u64 %0, t; }" : "=r"(a) : "l"(p));
    return a;
}
__device__ __forceinline__ void cp_async16(uint32_t dst, const void* src, bool ok) {
    asm volatile("cp.async.ca.shared.global [%0], [%1], 16, %2;"
                 :: "r"(dst), "l"(src), "r"(ok ? 16 : 0) : "memory");
}
#define CP_COMMIT() asm volatile("cp.async.commit_group;" ::: "memory")
#define CP_WAIT(n)  asm volatile("cp.async.wait_group %0;" :: "n"(n) : "memory")

__device__ __forceinline__ void ldmx4(uint32_t r[4], uint32_t addr) {
    asm volatile("ldmatrix.sync.aligned.m8n8.x4.shared.b16 {%0,%1,%2,%3}, [%4];"
                 : "=r"(r[0]), "=r"(r[1]), "=r"(r[2]), "=r"(r[3]) : "r"(addr));
}
__device__ __forceinline__ void mma_f16(float c[4], const uint32_t a[4],
                                        uint32_t b0, uint32_t b1) {
    asm volatile(
        "mma.sync.aligned.m16n8k16.row.col.f32.f16.f16.f32 "
        "{%0,%1,%2,%3}, {%4,%5,%6,%7}, {%8,%9}, {%0,%1,%2,%3};\n"
        : "+f"(c[0]), "+f"(c[1]), "+f"(c[2]), "+f"(c[3])
        : "r"(a[0]), "r"(a[1]), "r"(a[2]), "r"(a[3]), "r"(b0), "r"(b1));
}
__device__ __forceinline__ float gelu_f(float x) {
    float x3 = x * x * x;
    return 0.5f * x * (1.0f + tanhf(0.7978845608028654f * (x + 0.044715f * x3)));
}

// ======================= templated fp16 mma.sync GEMM (R12 champion) =======
#define BKH 64
#define NSTAGE 3

template <int WM, int WN, int NT2>
__global__ void __launch_bounds__(256, (WM == 2 ? 3 : 2))
gemm_h(const __half* __restrict__ A, const __half* __restrict__ Bt,
       const float* __restrict__ bias, const float* __restrict__ res,
       float* __restrict__ Cf, __half* __restrict__ Ch,
       int M, int N, int K, int act,
       float* __restrict__ sumOut, float* __restrict__ ssqOut) {
    constexpr int BM_ = WM * 32;
    constexpr int A_TILE = BM_ * 128;
    constexpr int STAGE = A_TILE + 16384;
    constexpr int TOT_ROWS = BM_ + 128;

    extern __shared__ char smem[];
    int tid = threadIdx.x;
    int wid = tid >> 5, lane = tid & 31;
    int g = lane >> 2, tg = lane & 3;
    int warp_m = wid % WM, warp_n = wid / WM;
    int m0 = blockIdx.y * BM_, n0 = blockIdx.x * 128;

    uint32_t sbase = smem_u32(smem);

    float acc[2][2 * NT2][4];
#pragma unroll
    for (int i = 0; i < 2; i++)
#pragma unroll
        for (int j = 0; j < 2 * NT2; j++)
#pragma unroll
            for (int l = 0; l < 4; l++) acc[i][j][l] = 0.f;

    auto load_stage = [&](int c) {
        int slot = c % NSTAGE;
        int k0 = c * BKH;
        uint32_t base = sbase + slot * STAGE;
#pragma unroll
        for (int u = tid; u < TOT_ROWS * 8; u += 256) {
            int row = u >> 3, q = u & 7;
            uint32_t off = (uint32_t)((q ^ (row & 7)) * 16);
            if (row < BM_) {
                bool ok = (m0 + row) < M;
                cp_async16(base + row * 128 + off,
                           A + (size_t)(m0 + row) * K + k0 + q * 8, ok);
            } else {
                int r2 = row - BM_;
                bool ok = (n0 + r2) < N;
                cp_async16(base + A_TILE + r2 * 128 + off,
                           Bt + (size_t)(n0 + r2) * K + k0 + q * 8, ok);
            }
        }
        CP_COMMIT();
    };

    const int NC = K / BKH;
    load_stage(0);
    load_stage(1);

    int rA = warp_m * 32 + ((lane >> 3) & 1) * 8 + (lane & 7);
    int kAh = (lane >> 4) & 1;
    int rB = warp_n * (NT2 * 16) + ((lane >> 4) & 1) * 8 + (lane & 7);
    int kBh = (lane >> 3) & 1;

    for (int c = 0; c < NC; c++) {
        if (c == NC - 1) { CP_WAIT(0); } else { CP_WAIT(1); }
        __syncthreads();
        if (c + 2 < NC) load_stage(c + 2);

        int slot = c % NSTAGE;
        uint32_t aBase = sbase + slot * STAGE;
        uint32_t bBase = aBase + A_TILE;

#pragma unroll
        for (int ks = 0; ks < 4; ks++) {
            uint32_t a[2][4];
#pragma unroll
            for (int mt = 0; mt < 2; mt++) {
                int row = rA + mt * 16;
                ldmx4(a[mt], aBase + row * 128 +
                      (uint32_t)(((2 * ks + kAh) ^ (row & 7)) * 16));
            }
            uint32_t b[NT2][4];
#pragma unroll
            for (int nt2 = 0; nt2 < NT2; nt2++) {
                int row = rB + nt2 * 16;
                ldmx4(b[nt2], bBase + row * 128 +
                      (uint32_t)(((2 * ks + kBh) ^ (row & 7)) * 16));
            }
#pragma unroll
            for (int mt = 0; mt < 2; mt++)
#pragma unroll
                for (int nt2 = 0; nt2 < NT2; nt2++) {
                    mma_f16(acc[mt][2 * nt2 + 0], a[mt], b[nt2][0], b[nt2][1]);
                    mma_f16(acc[mt][2 * nt2 + 1], a[mt], b[nt2][2], b[nt2][3]);
                }
        }
    }

    // epilogue (+ optional per-row stats)
#pragma unroll
    for (int mt = 0; mt < 2; mt++) {
#pragma unroll
        for (int hh = 0; hh < 2; hh++) {
            int row = m0 + warp_m * 32 + mt * 16 + g + hh * 8;
            bool rok = row < M;
            const float* rrow = (rok && res) ? res + (size_t)row * N : nullptr;
            float ps_ = 0.f, qs_ = 0.f;
#pragma unroll
            for (int j = 0; j < 2 * NT2; j++) {
                if (!rok) continue;
                int col = n0 + warp_n * (NT2 * 16) + (j >> 1) * 16 + (j & 1) * 8 + 2 * tg;
                float v0 = acc[mt][j][hh * 2 + 0] + bias[col];
                float v1 = acc[mt][j][hh * 2 + 1] + bias[col + 1];
                if (act == 1) { v0 = gelu_f(v0); v1 = gelu_f(v1); }
                if (rrow) { v0 += rrow[col]; v1 += rrow[col + 1]; }
                if (Ch) {
                    *(__half2*)(Ch + (size_t)row * N + col) = __floats2half2_rn(v0, v1);
                } else {
                    float2 o; o.x = v0; o.y = v1;
                    *(float2*)(Cf + (size_t)row * N + col) = o;
                }
                ps_ += v0 + v1;
                qs_ += v0 * v0 + v1 * v1;
            }
            if (sumOut) {
                ps_ += __shfl_xor_sync(0xffffffffu, ps_, 1);
                qs_ += __shfl_xor_sync(0xffffffffu, qs_, 1);
                ps_ += __shfl_xor_sync(0xffffffffu, ps_, 2);
                qs_ += __shfl_xor_sync(0xffffffffu, qs_, 2);
                if (rok && tg == 0) {
                    atomicAdd(&sumOut[row], ps_);
                    atomicAdd(&ssqOut[row], qs_);
                }
            }
        }
    }
}

#define SMEM_A (NSTAGE * (128 * 128 + 16384))  // 98304
#define SMEM_B (NSTAGE * (64 * 128 + 16384))   // 73728

// ======================= unified weight prep (64x64 float4 tiles) ==========
#define TPW  192
#define TSQ  256
#define TW1  1024
#define Z_PW   0
#define Z_WQ   (Z_PW + TPW)
#define Z_WK   (Z_WQ + NLAYER*TSQ)
#define Z_WV   (Z_WK + NLAYER*TSQ)
#define Z_WO   (Z_WV + NLAYER*TSQ)
#define Z_W1   (Z_WO + NLAYER*TSQ)
#define Z_W2   (Z_W1 + NLAYER*TW1)
#define Z_BIAS (Z_W2 + NLAYER*TW1)
#define Z_TOT  (Z_BIAS + 72)

__global__ void __launch_bounds__(256)
wprep_kernel(const float* __restrict__ pw,
             const float* __restrict__ wq, const float* __restrict__ wk,
             const float* __restrict__ wv, const float* __restrict__ wo,
             const float* __restrict__ w1, const float* __restrict__ w2,
             const float* __restrict__ bq, const float* __restrict__ bk,
             const float* __restrict__ bv,
             __half* __restrict__ pwt, __half* __restrict__ wqkvt,
             __half* __restrict__ wot, __half* __restrict__ w1t,
             __half* __restrict__ w2t, float* __restrict__ bqkv) {
    __shared__ float t[64][65];
    int z = blockIdx.x;
    int tid = threadIdx.x;
    const size_t DD = (size_t)DMODEL * DMODEL;
    const size_t DM = (size_t)DMODEL * DMLP;

    auto tr = [&](const float* ip, __half* op, int R, int C, int tx, int ty) {
        int c0 = tx * 64, r0 = ty * 64;
#pragma unroll
        for (int it = 0; it < 4; it++) {
            int idx = it * 256 + tid;
            int r = idx >> 4, c4 = (idx & 15) * 4;
            float4 v = *(const float4*)(ip + (size_t)(r0 + r) * C + c0 + c4);
            t[r][c4 + 0] = v.x; t[r][c4 + 1] = v.y;
            t[r][c4 + 2] = v.z; t[r][c4 + 3] = v.w;
        }
        __syncthreads();
#pragma unroll
        for (int it = 0; it < 4; it++) {
            int idx = it * 256 + tid;
            int oc = idx >> 4, r4 = (idx & 15) * 4;
            __half2 h0 = __floats2half2_rn(t[r4 + 0][oc], t[r4 + 1][oc]);
            __half2 h1 = __floats2half2_rn(t[r4 + 2][oc], t[r4 + 3][oc]);
            uint2 pk; pk.x = *(uint32_t*)&h0; pk.y = *(uint32_t*)&h1;
            *(uint2*)(op + (size_t)(c0 + oc) * R + r0 + r4) = pk;
        }
    };

    if (z < Z_WQ) {
        int r = z - Z_PW;
        tr(pw, pwt, PDIM, DMODEL, r % 16, r / 16);
    } else if (z < Z_WK) {
        int r = z - Z_WQ; int l = r / TSQ; r %= TSQ;
        tr(wq + l * DD, wqkvt + l * 3 * DD, DMODEL, DMODEL, r % 16, r / 16);
    } else if (z < Z_WV) {
        int r = z - Z_WK; int l = r / TSQ; r %= TSQ;
        tr(wk + l * DD, wqkvt + l * 3 * DD + DD, DMODEL, DMODEL, r % 16, r / 16);
    } else if (z < Z_WO) {
        int r = z - Z_WV; int l = r / TSQ; r %= TSQ;
        tr(wv + l * DD, wqkvt + l * 3 * DD + 2 * DD, DMODEL, DMODEL, r % 16, r / 16);
    } else if (z < Z_W1) {
        int r = z - Z_WO; int l = r / TSQ; r %= TSQ;
        tr(wo + l * DD, wot + l * DD, DMODEL, DMODEL, r % 16, r / 16);
    } else if (z < Z_W2) {
        int r = z - Z_W1; int l = r / TW1; r %= TW1;
        tr(w1 + l * DM, w1t + l * DM, DMODEL, DMLP, r % 64, r / 64);
    } else if (z < Z_BIAS) {
        int r = z - Z_W2; int l = r / TW1; r %= TW1;
        tr(w2 + l * DM, w2t + l * DM, DMLP, DMODEL, r % 16, r / 16);
    } else {
        int idx = (z - Z_BIAS) * 256 + tid;
        if (idx < NLAYER * QKVN) {
            int l = idx / QKVN, j = idx % QKVN;
            float v;
            if (j < DMODEL) v = bq[l * DMODEL + j];
            else if (j < 2 * DMODEL) v = bk[l * DMODEL + j - DMODEL];
            else v = bv[l * DMODEL + j - 2 * DMODEL];
            bqkv[idx] = v;
        }
    }
}

// ======================= patchify kept tokens only =======================
__global__ void patchify_keep_kernel(const float* __restrict__ imgs,
                                     const int* __restrict__ keep,
                                     __half* __restrict__ out) {
    int idx = blockIdx.x * blockDim.x + threadIdx.x;
    if (idx >= NKEPT * PDIM) return;
    int j = idx % PDIM;
    int t = idx / PDIM;
    int n = t / KEEP, s = t % KEEP;
    int l = keep[n * KEEP + s];
    int c  = j % 3;
    int px = (j / 3) % 16;
    int py = j / 48;
    int pw = l % 14;
    int ph = l / 14;
    out[idx] = __float2half_rn(imgs[(((size_t)n * 224 + ph * 16 + py) * 224 + pw * 16 + px) * 3 + c]);
}

// ======================= ranking / mask =======================
__global__ void rank_kernel(const float* __restrict__ noise, int* __restrict__ keep,
                            float* __restrict__ mask_out) {
    int n = blockIdx.x;
    __shared__ float ns[LSEQ];
    int i = threadIdx.x;
    if (i < LSEQ) ns[i] = noise[n * LSEQ + i];
    __syncthreads();
    if (i < LSEQ) {
        float my = ns[i];
        int r = 0;
        for (int j = 0; j < LSEQ; j++) {
            float vj = ns[j];
            r += (vj < my) || (vj == my && j < i);
        }
        if (r < KEEP) keep[n * KEEP + r] = i;
        mask_out[n * LSEQ + i] = (r < KEEP) ? 0.0f : 1.0f;
    }
}

// ======================= zero stats =======================
__global__ void zero2_kernel(float* __restrict__ a, float* __restrict__ b) {
    int i = blockIdx.x * 256 + threadIdx.x;
    if (i < NSLOT * NTOK) { a[i] = 0.f; b[i] = 0.f; }
}

// ======================= gather: xg + pos -> x, + stats slot0 =============
__global__ void gather_kernel(const float* __restrict__ xg, const float* __restrict__ pos,
                              const float* __restrict__ cls, const int* __restrict__ keep,
                              float* __restrict__ x, float* __restrict__ sum0,
                              float* __restrict__ ssq0) {
    int b = blockIdx.x;
    int n = b / SEQ, s = b % SEQ;
    float* xo = x + (size_t)b * DMODEL;
    int tid = threadIdx.x;
    float ls = 0.f, lq = 0.f;
    if (s == 0) {
        for (int d = tid; d < DMODEL; d += 256) {
            float v = cls[d]; xo[d] = v; ls += v; lq += v * v;
        }
    } else {
        int id = keep[n * KEEP + s - 1];
        const float* src = xg + ((size_t)n * KEEP + s - 1) * DMODEL;
        const float* pp  = pos + (size_t)id * DMODEL;
        for (int d = tid; d < DMODEL; d += 256) {
            float v = src[d] + pp[d]; xo[d] = v; ls += v; lq += v * v;
        }
    }
    __shared__ float rs[256], rq[256];
    rs[tid] = ls; rq[tid] = lq; __syncthreads();
    for (int o = 128; o > 0; o >>= 1) {
        if (tid < o) { rs[tid] += rs[tid + o]; rq[tid] += rq[tid + o]; }
        __syncthreads();
    }
    if (tid == 0) { sum0[b] = rs[0]; ssq0[b] = rq[0]; }
}

// ======================= LN apply (stats precomputed) =======================
__global__ void ln_apply(const float* __restrict__ x, const float* __restrict__ s,
                         const float* __restrict__ b, const float* __restrict__ sum,
                         const float* __restrict__ ssq, float* __restrict__ yf,
                         __half* __restrict__ yh) {
    int row = blockIdx.x;
    int d = threadIdx.x * 8;
    float m = sum[row] * (1.0f / DMODEL);
    float var = ssq[row] * (1.0f / DMODEL) - m * m;
    float rstd = rsqrtf(var + 1e-6f);
    const float* xr = x + (size_t)row * DMODEL + d;
    float4 u0 = *(const float4*)(xr);
    float4 u1 = *(const float4*)(xr + 4);
    float4 s0 = *(const float4*)(s + d);
    float4 s1 = *(const float4*)(s + d + 4);
    float4 b0 = *(const float4*)(b + d);
    float4 b1 = *(const float4*)(b + d + 4);
    float v[8];
    v[0] = (u0.x - m) * rstd * s0.x + b0.x;
    v[1] = (u0.y - m) * rstd * s0.y + b0.y;
    v[2] = (u0.z - m) * rstd * s0.z + b0.z;
    v[3] = (u0.w - m) * rstd * s0.w + b0.w;
    v[4] = (u1.x - m) * rstd * s1.x + b1.x;
    v[5] = (u1.y - m) * rstd * s1.y + b1.y;
    v[6] = (u1.z - m) * rstd * s1.z + b1.z;
    v[7] = (u1.w - m) * rstd * s1.w + b1.w;
    if (yh) {
        __half2 hh[4];
        hh[0] = __floats2half2_rn(v[0], v[1]);
        hh[1] = __floats2half2_rn(v[2], v[3]);
        hh[2] = __floats2half2_rn(v[4], v[5]);
        hh[3] = __floats2half2_rn(v[6], v[7]);
        *(uint4*)(yh + (size_t)row * DMODEL + d) = *(uint4*)hh;
    } else {
        *(float4*)(yf + (size_t)row * DMODEL + d) = make_float4(v[0], v[1], v[2], v[3]);
        *(float4*)(yf + (size_t)row * DMODEL + d + 4) = make_float4(v[4], v[5], v[6], v[7]);
    }
}

// ======================= attention (float4 QK loop, 8 warps) ==============
__global__ void __launch_bounds__(256)
attn_kernel(const __half* __restrict__ qkv, __half* __restrict__ o) {
    int nh = blockIdx.x;
    int n = nh / NHEAD, h = nh % NHEAD;
    __shared__ float Ks[SEQ][DHEAD + 4];       // 272B rows, 16B aligned
    __shared__ __half2 Vs[SEQ][DHEAD / 2];
    __shared__ float ps[8][SEQ];
    __shared__ float qs[8][DHEAD];
    int tid = threadIdx.x;
    int w = tid >> 5, lane = tid & 31;

    const __half* qb = qkv + (size_t)n * SEQ * QKVN + h * DHEAD;
    const __half* kb = qb + DMODEL;
    const __half* vb = qb + 2 * DMODEL;
    __half* ob = o + (size_t)n * SEQ * DMODEL + h * DHEAD;

    for (int idx = tid; idx < SEQ * DHEAD; idx += 256) {
        int j = idx / DHEAD, d = idx % DHEAD;
        Ks[j][d] = __half2float(kb[(size_t)j * QKVN + d]);
    }
    for (int idx = tid; idx < SEQ * (DHEAD / 2); idx += 256) {
        int j = idx >> 5, d2 = idx & 31;
        Vs[j][d2] = *(const __half2*)(vb + (size_t)j * QKVN + 2 * d2);
    }
    __syncthreads();

    for (int si = w; si < SEQ; si += 8) {
        qs[w][lane]      = __half2float(qb[(size_t)si * QKVN + lane]);
        qs[w][lane + 32] = __half2float(qb[(size_t)si * QKVN + lane + 32]);
        __syncwarp();
        float a[4] = {0.f, 0.f, 0.f, 0.f};
#pragma unroll
        for (int d4 = 0; d4 < DHEAD; d4 += 4) {
            float4 qf = *(const float4*)&qs[w][d4];
#pragma unroll
            for (int m = 0; m < 4; m++) {
                int j = lane + m * 32;
                if (j < SEQ) {
                    float4 kf = *(const float4*)&Ks[j][d4];
                    a[m] += qf.x * kf.x + qf.y * kf.y + qf.z * kf.z + qf.w * kf.w;
                }
            }
        }
        float sc[4];
#pragma unroll
        for (int m = 0; m < 4; m++) {
            int j = lane + m * 32;
            sc[m] = (j < SEQ) ? a[m] * 0.125f : -1e30f;
        }
        float mx = fmaxf(fmaxf(sc[0], sc[1]), fmaxf(sc[2], sc[3]));
#pragma unroll
        for (int off = 16; off > 0; off >>= 1) mx = fmaxf(mx, __shfl_xor_sync(0xffffffffu, mx, off));
        float sum = 0.f;
#pragma unroll
        for (int m = 0; m < 4; m++) {
            int j = lane + m * 32;
            float e = (j < SEQ) ? __expf(sc[m] - mx) : 0.f;
            sc[m] = e; sum += e;
        }
#pragma unroll
        for (int off = 16; off > 0; off >>= 1) sum += __shfl_xor_sync(0xffffffffu, sum, off);
        float inv = 1.0f / sum;
#pragma unroll
        for (int m = 0; m < 4; m++) {
            int j = lane + m * 32;
            if (j < SEQ) ps[w][j] = sc[m] * inv;
        }
        __syncwarp();
        float a0 = 0.f, a1 = 0.f;
        for (int j = 0; j < SEQ; j++) {
            float pv = ps[w][j];
            float2 vf = __half22float2(Vs[j][lane]);
            a0 += pv * vf.x;
            a1 += pv * vf.y;
        }
        *(__half2*)(ob + (size_t)si * DMODEL + 2 * lane) = __floats2half2_rn(a0, a1);
        __syncwarp();
    }
}

// ======================= launch =======================
extern "C" void kernel_launch(void* const* d_in, const int* in_sizes, int n_in,
                              void* d_out, int out_size) {
    const float* imgs    = (const float*)d_in[0];
    const float* noise   = (const float*)d_in[1];
    const float* patch_w = (const float*)d_in[2];
    const float* patch_b = (const float*)d_in[3];
    const float* pos_emb = (const float*)d_in[4];
    const float* cls_tok = (const float*)d_in[5];
    const float* ln1_s   = (const float*)d_in[6];
    const float* ln1_b   = (const float*)d_in[7];
    const float* wq      = (const float*)d_in[8];
    const float* bq      = (const float*)d_in[9];
    const float* wk      = (const float*)d_in[10];
    const float* bk      = (const float*)d_in[11];
    const float* wv      = (const float*)d_in[12];
    const float* bv      = (const float*)d_in[13];
    const float* wo      = (const float*)d_in[14];
    const float* bo      = (const float*)d_in[15];
    const float* ln2_s   = (const float*)d_in[16];
    const float* ln2_b   = (const float*)d_in[17];
    const float* w1      = (const float*)d_in[18];
    const float* b1      = (const float*)d_in[19];
    const float* w2      = (const float*)d_in[20];
    const float* b2      = (const float*)d_in[21];
    const float* lnf_s   = (const float*)d_in[22];
    const float* lnf_b   = (const float*)d_in[23];

    float* out = (float*)d_out;
    float* out_mask = out + (size_t)NTOK * DMODEL;

    __half *patches, *y, *qkv, *ao, *h1, *pwt, *wqkvt, *wot, *w1t, *w2t;
    float *x0, *x, *bqkv, *gsum, *gssq;
    int* keep;
    cudaGetSymbolAddress((void**)&patches, g_patches);
    cudaGetSymbolAddress((void**)&x0, g_x0);
    cudaGetSymbolAddress((void**)&x,  g_x);
    cudaGetSymbolAddress((void**)&y,  g_y);
    cudaGetSymbolAddress((void**)&qkv, g_qkv);
    cudaGetSymbolAddress((void**)&ao, g_ao);
    cudaGetSymbolAddress((void**)&h1, g_h1);
    cudaGetSymbolAddress((void**)&keep, g_keep);
    cudaGetSymbolAddress((void**)&pwt, g_pwt);
    cudaGetSymbolAddress((void**)&wqkvt, g_wqkvt);
    cudaGetSymbolAddress((void**)&wot, g_wot);
    cudaGetSymbolAddress((void**)&w1t, g_w1t);
    cudaGetSymbolAddress((void**)&w2t, g_w2t);
    cudaGetSymbolAddress((void**)&bqkv, g_bqkv);
    cudaGetSymbolAddress((void**)&gsum, g_sum);
    cudaGetSymbolAddress((void**)&gssq, g_ssq);

    cudaFuncSetAttribute(gemm_h<4, 2, 4>, cudaFuncAttributeMaxDynamicSharedMemorySize, SMEM_A);
    cudaFuncSetAttribute(gemm_h<2, 4, 2>, cudaFuncAttributeMaxDynamicSharedMemorySize, SMEM_B);

    rank_kernel<<<NIMG, 224>>>(noise, keep, out_mask);
    patchify_keep_kernel<<<(NKEPT * PDIM + 255) / 256, 256>>>(imgs, keep, patches);
    zero2_kernel<<<(NSLOT * NTOK + 255) / 256, 256>>>(gsum, gssq);
    wprep_kernel<<<Z_TOT, 256>>>(patch_w, wq, wk, wv, wo, w1, w2, bq, bk, bv,
                                 pwt, wqkvt, wot, w1t, w2t, bqkv);

    // patch embed on kept tokens only: M=3136, N=1024
    {
        dim3 grid(DMODEL / 128, (NKEPT + 127) / 128);
        gemm_h<4, 2, 4><<<grid, 256, SMEM_A>>>(patches, pwt, patch_b, nullptr, x0, nullptr,
                                               NKEPT, DMODEL, PDIM, 0, nullptr, nullptr);
    }
    gather_kernel<<<NTOK, 256>>>(x0, pos_emb, cls_tok, keep, x, gsum, gssq);

    dim3 gQKV(QKVN / 128, (NTOK + 127) / 128);    // 24 x 25 (128-tile)
    dim3 gD64(DMODEL / 128, (NTOK + 63) / 64);    // 8 x 50  (64-tile, 3 CTA/SM)
    dim3 gM(DMLP / 128, (NTOK + 127) / 128);      // 32 x 25 (128-tile)

    for (int i = 0; i < NLAYER; i++) {
        const __half* wqkv_i = wqkvt + (size_t)i * 3 * DMODEL * DMODEL;
        const __half* wo_i = wot + (size_t)i * DMODEL * DMODEL;
        const __half* w1_i = w1t + (size_t)i * DMODEL * DMLP;
        const __half* w2_i = w2t + (size_t)i * DMLP * DMODEL;
        float* s0 = gsum + (size_t)(2 * i) * NTOK;
        float* q0 = gssq + (size_t)(2 * i) * NTOK;
        float* s1 = gsum + (size_t)(2 * i + 1) * NTOK;
        float* q1 = gssq + (size_t)(2 * i + 1) * NTOK;
        float* s2 = gsum + (size_t)(2 * i + 2) * NTOK;
        float* q2 = gssq + (size_t)(2 * i + 2) * NTOK;

        ln_apply<<<NTOK, 128>>>(x, ln1_s + i * DMODEL, ln1_b + i * DMODEL, s0, q0, nullptr, y);
        gemm_h<4, 2, 4><<<gQKV, 256, SMEM_A>>>(y, wqkv_i, bqkv + (size_t)i * QKVN, nullptr,
                                               nullptr, qkv, NTOK, QKVN, DMODEL, 0,
                                               nullptr, nullptr);
        attn_kernel<<<NIMG * NHEAD, 256>>>(qkv, ao);
        gemm_h<2, 4, 2><<<gD64, 256, SMEM_B>>>(ao, wo_i, bo + i * DMODEL, x, x, nullptr,
                                               NTOK, DMODEL, DMODEL, 0, s1, q1);
        ln_apply<<<NTOK, 128>>>(x, ln2_s + i * DMODEL, ln2_b + i * DMODEL, s1, q1, nullptr, y);
        gemm_h<4, 2, 4><<<gM, 256, SMEM_A>>>(y, w1_i, b1 + i * DMLP, nullptr,
                                             nullptr, h1, NTOK, DMLP, DMODEL, 1,
                                             nullptr, nullptr);
        gemm_h<2, 4, 2><<<gD64, 256, SMEM_B>>>(h1, w2_i, b2 + i * DMODEL, x, x, nullptr,
                                               NTOK, DMODEL, DMLP, 0, s2, q2);
    }
    ln_apply<<<NTOK, 128>>>(x, lnf_s, lnf_b, gsum + (size_t)12 * NTOK,
                            gssq + (size_t)12 * NTOK, out, nullptr);
}

// round 17
// speedup vs baseline: 1.1440x; 1.0064x over previous
#include <cuda_runtime.h>
#include <cuda_fp16.h>
#include <cstdint>
#include <math.h>

// Problem constants
#define NIMG 32
#define LSEQ 196
#define KEEP 98
#define SEQ  99
#define DMODEL 1024
#define NHEAD 16
#define DHEAD 64
#define DMLP 4096
#define NLAYER 6
#define PDIM 768
#define NTOK (NIMG*SEQ)   // 3168
#define NKEPT (NIMG*KEEP) // 3136
#define QKVN (3*DMODEL)   // 3072
#define NSLOT 13

// ======================= scratch (device globals) =======================
__device__ __half g_patches[(size_t)NKEPT*PDIM];
__device__ float  g_x0[(size_t)NKEPT*DMODEL];
__device__ float  g_x [(size_t)NTOK*DMODEL];
__device__ __half g_y [(size_t)NTOK*DMODEL];
__device__ __half g_qkv[(size_t)NTOK*QKVN];
__device__ __half g_ao[(size_t)NTOK*DMODEL];
__device__ __half g_h1[(size_t)NTOK*DMLP];
__device__ int    g_keep[NIMG*KEEP];
__device__ float  g_sum[(size_t)NSLOT*NTOK];
__device__ float  g_ssq[(size_t)NSLOT*NTOK];
// transposed half weights (K-major, [N,K])
__device__ __half g_pwt[(size_t)DMODEL*PDIM];
__device__ __half g_wqkvt[(size_t)NLAYER*QKVN*DMODEL];
__device__ __half g_wot[(size_t)NLAYER*DMODEL*DMODEL];
__device__ __half g_w1t[(size_t)NLAYER*DMLP*DMODEL];
__device__ __half g_w2t[(size_t)NLAYER*DMODEL*DMLP];
__device__ float  g_bqkv[(size_t)NLAYER*QKVN];

// ======================= helpers =======================
__device__ __forceinline__ uint32_t smem_u32(const void* p) {
    uint32_t a;
    asm("{ .reg .u64 t; cvta.to.shared.u64 t, %1; cvt.u32.u64 %0, t; }" : "=r"(a) : "l"(p));
    return a;
}
__device__ __forceinline__ void cp_async16(uint32_t dst, const void* src, bool ok) {
    asm volatile("cp.async.ca.shared.global [%0], [%1], 16, %2;"
                 :: "r"(dst), "l"(src), "r"(ok ? 16 : 0) : "memory");
}
#define CP_COMMIT() asm volatile("cp.async.commit_group;" ::: "memory")
#define CP_WAIT(n)  asm volatile("cp.async.wait_group %0;" :: "n"(n) : "memory")

__device__ __forceinline__ void ldmx4(uint32_t r[4], uint32_t addr) {
    asm volatile("ldmatrix.sync.aligned.m8n8.x4.shared.b16 {%0,%1,%2,%3}, [%4];"
                 : "=r"(r[0]), "=r"(r[1]), "=r"(r[2]), "=r"(r[3]) : "r"(addr));
}
__device__ __forceinline__ void mma_f16(float c[4], const uint32_t a[4],
                                        uint32_t b0, uint32_t b1) {
    asm volatile(
        "mma.sync.aligned.m16n8k16.row.col.f32.f16.f16.f32 "
        "{%0,%1,%2,%3}, {%4,%5,%6,%7}, {%8,%9}, {%0,%1,%2,%3};\n"
        : "+f"(c[0]), "+f"(c[1]), "+f"(c[2]), "+f"(c[3])
        : "r"(a[0]), "r"(a[1]), "r"(a[2]), "r"(a[3]), "r"(b0), "r"(b1));
}
// gelu(x) = 0.5x(1+tanh(u)) = x * sigmoid(2u), u = 0.79788456(x + 0.044715 x^3)
__device__ __forceinline__ float gelu_f(float x) {
    float z = 1.5957691216057308f * (x + 0.044715f * x * x * x);
    return x / (1.0f + __expf(-z));
}

// ======================= templated fp16 mma.sync GEMM (champion) ==========
#define BKH 64
#define NSTAGE 3

template <int WM, int WN, int NT2>
__global__ void __launch_bounds__(256, (WM == 2 ? 3 : 2))
gemm_h(const __half* __restrict__ A, const __half* __restrict__ Bt,
       const float* __restrict__ bias, const float* __restrict__ res,
       float* __restrict__ Cf, __half* __restrict__ Ch,
       int M, int N, int K, int act,
       float* __restrict__ sumOut, float* __restrict__ ssqOut) {
    constexpr int BM_ = WM * 32;
    constexpr int A_TILE = BM_ * 128;
    constexpr int STAGE = A_TILE + 16384;
    constexpr int TOT_ROWS = BM_ + 128;

    extern __shared__ char smem[];
    int tid = threadIdx.x;
    int wid = tid >> 5, lane = tid & 31;
    int g = lane >> 2, tg = lane & 3;
    int warp_m = wid % WM, warp_n = wid / WM;
    int m0 = blockIdx.y * BM_, n0 = blockIdx.x * 128;

    uint32_t sbase = smem_u32(smem);

    float acc[2][2 * NT2][4];
#pragma unroll
    for (int i = 0; i < 2; i++)
#pragma unroll
        for (int j = 0; j < 2 * NT2; j++)
#pragma unroll
            for (int l = 0; l < 4; l++) acc[i][j][l] = 0.f;

    auto load_stage = [&](int c) {
        int slot = c % NSTAGE;
        int k0 = c * BKH;
        uint32_t base = sbase + slot * STAGE;
#pragma unroll
        for (int u = tid; u < TOT_ROWS * 8; u += 256) {
            int row = u >> 3, q = u & 7;
            uint32_t off = (uint32_t)((q ^ (row & 7)) * 16);
            if (row < BM_) {
                bool ok = (m0 + row) < M;
                cp_async16(base + row * 128 + off,
                           A + (size_t)(m0 + row) * K + k0 + q * 8, ok);
            } else {
                int r2 = row - BM_;
                bool ok = (n0 + r2) < N;
                cp_async16(base + A_TILE + r2 * 128 + off,
                           Bt + (size_t)(n0 + r2) * K + k0 + q * 8, ok);
            }
        }
        CP_COMMIT();
    };

    const int NC = K / BKH;
    load_stage(0);
    load_stage(1);

    int rA = warp_m * 32 + ((lane >> 3) & 1) * 8 + (lane & 7);
    int kAh = (lane >> 4) & 1;
    int rB = warp_n * (NT2 * 16) + ((lane >> 4) & 1) * 8 + (lane & 7);
    int kBh = (lane >> 3) & 1;

    for (int c = 0; c < NC; c++) {
        if (c == NC - 1) { CP_WAIT(0); } else { CP_WAIT(1); }
        __syncthreads();
        if (c + 2 < NC) load_stage(c + 2);

        int slot = c % NSTAGE;
        uint32_t aBase = sbase + slot * STAGE;
        uint32_t bBase = aBase + A_TILE;

#pragma unroll
        for (int ks = 0; ks < 4; ks++) {
            uint32_t a[2][4];
#pragma unroll
            for (int mt = 0; mt < 2; mt++) {
                int row = rA + mt * 16;
                ldmx4(a[mt], aBase + row * 128 +
                      (uint32_t)(((2 * ks + kAh) ^ (row & 7)) * 16));
            }
            uint32_t b[NT2][4];
#pragma unroll
            for (int nt2 = 0; nt2 < NT2; nt2++) {
                int row = rB + nt2 * 16;
                ldmx4(b[nt2], bBase + row * 128 +
                      (uint32_t)(((2 * ks + kBh) ^ (row & 7)) * 16));
            }
#pragma unroll
            for (int mt = 0; mt < 2; mt++)
#pragma unroll
                for (int nt2 = 0; nt2 < NT2; nt2++) {
                    mma_f16(acc[mt][2 * nt2 + 0], a[mt], b[nt2][0], b[nt2][1]);
                    mma_f16(acc[mt][2 * nt2 + 1], a[mt], b[nt2][2], b[nt2][3]);
                }
        }
    }

    // epilogue (+ optional per-row stats)
#pragma unroll
    for (int mt = 0; mt < 2; mt++) {
#pragma unroll
        for (int hh = 0; hh < 2; hh++) {
            int row = m0 + warp_m * 32 + mt * 16 + g + hh * 8;
            bool rok = row < M;
            const float* rrow = (rok && res) ? res + (size_t)row * N : nullptr;
            float ps_ = 0.f, qs_ = 0.f;
#pragma unroll
            for (int j = 0; j < 2 * NT2; j++) {
                if (!rok) continue;
                int col = n0 + warp_n * (NT2 * 16) + (j >> 1) * 16 + (j & 1) * 8 + 2 * tg;
                float v0 = acc[mt][j][hh * 2 + 0] + bias[col];
                float v1 = acc[mt][j][hh * 2 + 1] + bias[col + 1];
                if (act == 1) { v0 = gelu_f(v0); v1 = gelu_f(v1); }
                if (rrow) { v0 += rrow[col]; v1 += rrow[col + 1]; }
                if (Ch) {
                    *(__half2*)(Ch + (size_t)row * N + col) = __floats2half2_rn(v0, v1);
                } else {
                    float2 o; o.x = v0; o.y = v1;
                    *(float2*)(Cf + (size_t)row * N + col) = o;
                }
                ps_ += v0 + v1;
                qs_ += v0 * v0 + v1 * v1;
            }
            if (sumOut) {
                ps_ += __shfl_xor_sync(0xffffffffu, ps_, 1);
                qs_ += __shfl_xor_sync(0xffffffffu, qs_, 1);
                ps_ += __shfl_xor_sync(0xffffffffu, ps_, 2);
                qs_ += __shfl_xor_sync(0xffffffffu, qs_, 2);
                if (rok && tg == 0) {
                    atomicAdd(&sumOut[row], ps_);
                    atomicAdd(&ssqOut[row], qs_);
                }
            }
        }
    }
}

#define SMEM_A (NSTAGE * (128 * 128 + 16384))  // 98304
#define SMEM_B (NSTAGE * (64 * 128 + 16384))   // 73728

// ======================= unified weight prep (64x64 float4 tiles) ==========
#define TPW  192
#define TSQ  256
#define TW1  1024
#define Z_PW   0
#define Z_WQ   (Z_PW + TPW)
#define Z_WK   (Z_WQ + NLAYER*TSQ)
#define Z_WV   (Z_WK + NLAYER*TSQ)
#define Z_WO   (Z_WV + NLAYER*TSQ)
#define Z_W1   (Z_WO + NLAYER*TSQ)
#define Z_W2   (Z_W1 + NLAYER*TW1)
#define Z_BIAS (Z_W2 + NLAYER*TW1)
#define Z_TOT  (Z_BIAS + 72)

__global__ void __launch_bounds__(256)
wprep_kernel(const float* __restrict__ pw,
             const float* __restrict__ wq, const float* __restrict__ wk,
             const float* __restrict__ wv, const float* __restrict__ wo,
             const float* __restrict__ w1, const float* __restrict__ w2,
             const float* __restrict__ bq, const float* __restrict__ bk,
             const float* __restrict__ bv,
             __half* __restrict__ pwt, __half* __restrict__ wqkvt,
             __half* __restrict__ wot, __half* __restrict__ w1t,
             __half* __restrict__ w2t, float* __restrict__ bqkv) {
    __shared__ float t[64][65];
    int z = blockIdx.x;
    int tid = threadIdx.x;
    const size_t DD = (size_t)DMODEL * DMODEL;
    const size_t DM = (size_t)DMODEL * DMLP;

    auto tr = [&](const float* ip, __half* op, int R, int C, int tx, int ty) {
        int c0 = tx * 64, r0 = ty * 64;
#pragma unroll
        for (int it = 0; it < 4; it++) {
            int idx = it * 256 + tid;
            int r = idx >> 4, c4 = (idx & 15) * 4;
            float4 v = *(const float4*)(ip + (size_t)(r0 + r) * C + c0 + c4);
            t[r][c4 + 0] = v.x; t[r][c4 + 1] = v.y;
            t[r][c4 + 2] = v.z; t[r][c4 + 3] = v.w;
        }
        __syncthreads();
#pragma unroll
        for (int it = 0; it < 4; it++) {
            int idx = it * 256 + tid;
            int oc = idx >> 4, r4 = (idx & 15) * 4;
            __half2 h0 = __floats2half2_rn(t[r4 + 0][oc], t[r4 + 1][oc]);
            __half2 h1 = __floats2half2_rn(t[r4 + 2][oc], t[r4 + 3][oc]);
            uint2 pk; pk.x = *(uint32_t*)&h0; pk.y = *(uint32_t*)&h1;
            *(uint2*)(op + (size_t)(c0 + oc) * R + r0 + r4) = pk;
        }
    };

    if (z < Z_WQ) {
        int r = z - Z_PW;
        tr(pw, pwt, PDIM, DMODEL, r % 16, r / 16);
    } else if (z < Z_WK) {
        int r = z - Z_WQ; int l = r / TSQ; r %= TSQ;
        tr(wq + l * DD, wqkvt + l * 3 * DD, DMODEL, DMODEL, r % 16, r / 16);
    } else if (z < Z_WV) {
        int r = z - Z_WK; int l = r / TSQ; r %= TSQ;
        tr(wk + l * DD, wqkvt + l * 3 * DD + DD, DMODEL, DMODEL, r % 16, r / 16);
    } else if (z < Z_WO) {
        int r = z - Z_WV; int l = r / TSQ; r %= TSQ;
        tr(wv + l * DD, wqkvt + l * 3 * DD + 2 * DD, DMODEL, DMODEL, r % 16, r / 16);
    } else if (z < Z_W1) {
        int r = z - Z_WO; int l = r / TSQ; r %= TSQ;
        tr(wo + l * DD, wot + l * DD, DMODEL, DMODEL, r % 16, r / 16);
    } else if (z < Z_W2) {
        int r = z - Z_W1; int l = r / TW1; r %= TW1;
        tr(w1 + l * DM, w1t + l * DM, DMODEL, DMLP, r % 64, r / 64);
    } else if (z < Z_BIAS) {
        int r = z - Z_W2; int l = r / TW1; r %= TW1;
        tr(w2 + l * DM, w2t + l * DM, DMLP, DMODEL, r % 16, r / 16);
    } else {
        int idx = (z - Z_BIAS) * 256 + tid;
        if (idx < NLAYER * QKVN) {
            int l = idx / QKVN, j = idx % QKVN;
            float v;
            if (j < DMODEL) v = bq[l * DMODEL + j];
            else if (j < 2 * DMODEL) v = bk[l * DMODEL + j - DMODEL];
            else v = bv[l * DMODEL + j - 2 * DMODEL];
            bqkv[idx] = v;
        }
    }
}

// ======================= patchify kept tokens only =======================
__global__ void patchify_keep_kernel(const float* __restrict__ imgs,
                                     const int* __restrict__ keep,
                                     __half* __restrict__ out) {
    int idx = blockIdx.x * blockDim.x + threadIdx.x;
    if (idx >= NKEPT * PDIM) return;
    int j = idx % PDIM;
    int t = idx / PDIM;
    int n = t / KEEP, s = t % KEEP;
    int l = keep[n * KEEP + s];
    int c  = j % 3;
    int px = (j / 3) % 16;
    int py = j / 48;
    int pw = l % 14;
    int ph = l / 14;
    out[idx] = __float2half_rn(imgs[(((size_t)n * 224 + ph * 16 + py) * 224 + pw * 16 + px) * 3 + c]);
}

// ======================= ranking / mask =======================
__global__ void rank_kernel(const float* __restrict__ noise, int* __restrict__ keep,
                            float* __restrict__ mask_out) {
    int n = blockIdx.x;
    __shared__ float ns[LSEQ];
    int i = threadIdx.x;
    if (i < LSEQ) ns[i] = noise[n * LSEQ + i];
    __syncthreads();
    if (i < LSEQ) {
        float my = ns[i];
        int r = 0;
        for (int j = 0; j < LSEQ; j++) {
            float vj = ns[j];
            r += (vj < my) || (vj == my && j < i);
        }
        if (r < KEEP) keep[n * KEEP + r] = i;
        mask_out[n * LSEQ + i] = (r < KEEP) ? 0.0f : 1.0f;
    }
}

// ======================= zero stats =======================
__global__ void zero2_kernel(float* __restrict__ a, float* __restrict__ b) {
    int i = blockIdx.x * 256 + threadIdx.x;
    if (i < NSLOT * NTOK) { a[i] = 0.f; b[i] = 0.f; }
}

// ======================= gather: xg + pos -> x, + stats slot0 =============
__global__ void gather_kernel(const float* __restrict__ xg, const float* __restrict__ pos,
                              const float* __restrict__ cls, const int* __restrict__ keep,
                              float* __restrict__ x, float* __restrict__ sum0,
                              float* __restrict__ ssq0) {
    int b = blockIdx.x;
    int n = b / SEQ, s = b % SEQ;
    float* xo = x + (size_t)b * DMODEL;
    int tid = threadIdx.x;
    float ls = 0.f, lq = 0.f;
    if (s == 0) {
        for (int d = tid; d < DMODEL; d += 256) {
            float v = cls[d]; xo[d] = v; ls += v; lq += v * v;
        }
    } else {
        int id = keep[n * KEEP + s - 1];
        const float* src = xg + ((size_t)n * KEEP + s - 1) * DMODEL;
        const float* pp  = pos + (size_t)id * DMODEL;
        for (int d = tid; d < DMODEL; d += 256) {
            float v = src[d] + pp[d]; xo[d] = v; ls += v; lq += v * v;
        }
    }
    __shared__ float rs[256], rq[256];
    rs[tid] = ls; rq[tid] = lq; __syncthreads();
    for (int o = 128; o > 0; o >>= 1) {
        if (tid < o) { rs[tid] += rs[tid + o]; rq[tid] += rq[tid + o]; }
        __syncthreads();
    }
    if (tid == 0) { sum0[b] = rs[0]; ssq0[b] = rq[0]; }
}

// ======================= LN apply (stats precomputed) =======================
__global__ void ln_apply(const float* __restrict__ x, const float* __restrict__ s,
                         const float* __restrict__ b, const float* __restrict__ sum,
                         const float* __restrict__ ssq, float* __restrict__ yf,
                         __half* __restrict__ yh) {
    int row = blockIdx.x;
    int d = threadIdx.x * 8;
    float m = sum[row] * (1.0f / DMODEL);
    float var = ssq[row] * (1.0f / DMODEL) - m * m;
    float rstd = rsqrtf(var + 1e-6f);
    const float* xr = x + (size_t)row * DMODEL + d;
    float4 u0 = *(const float4*)(xr);
    float4 u1 = *(const float4*)(xr + 4);
    float4 s0 = *(const float4*)(s + d);
    float4 s1 = *(const float4*)(s + d + 4);
    float4 b0 = *(const float4*)(b + d);
    float4 b1 = *(const float4*)(b + d + 4);
    float v[8];
    v[0] = (u0.x - m) * rstd * s0.x + b0.x;
    v[1] = (u0.y - m) * rstd * s0.y + b0.y;
    v[2] = (u0.z - m) * rstd * s0.z + b0.z;
    v[3] = (u0.w - m) * rstd * s0.w + b0.w;
    v[4] = (u1.x - m) * rstd * s1.x + b1.x;
    v[5] = (u1.y - m) * rstd * s1.y + b1.y;
    v[6] = (u1.z - m) * rstd * s1.z + b1.z;
    v[7] = (u1.w - m) * rstd * s1.w + b1.w;
    if (yh) {
        __half2 hh[4];
        hh[0] = __floats2half2_rn(v[0], v[1]);
        hh[1] = __floats2half2_rn(v[2], v[3]);
        hh[2] = __floats2half2_rn(v[4], v[5]);
        hh[3] = __floats2half2_rn(v[6], v[7]);
        *(uint4*)(yh + (size_t)row * DMODEL + d) = *(uint4*)hh;
    } else {
        *(float4*)(yf + (size_t)row * DMODEL + d) = make_float4(v[0], v[1], v[2], v[3]);
        *(float4*)(yf + (size_t)row * DMODEL + d + 4) = make_float4(v[4], v[5], v[6], v[7]);
    }
}

// ======================= attention (float4 QK + PV loops, 8 warps) ========
__global__ void __launch_bounds__(256)
attn_kernel(const __half* __restrict__ qkv, __half* __restrict__ o) {
    int nh = blockIdx.x;
    int n = nh / NHEAD, h = nh % NHEAD;
    __shared__ float Ks[SEQ][DHEAD + 4];       // 272B rows
    __shared__ __half2 Vs[100][DHEAD / 2];     // row 99 zeroed
    __shared__ float ps[8][100];               // 400B rows, [99] zeroed
    __shared__ float qs[8][DHEAD];
    int tid = threadIdx.x;
    int w = tid >> 5, lane = tid & 31;

    const __half* qb = qkv + (size_t)n * SEQ * QKVN + h * DHEAD;
    const __half* kb = qb + DMODEL;
    const __half* vb = qb + 2 * DMODEL;
    __half* ob = o + (size_t)n * SEQ * DMODEL + h * DHEAD;

    for (int idx = tid; idx < SEQ * DHEAD; idx += 256) {
        int j = idx / DHEAD, d = idx % DHEAD;
        Ks[j][d] = __half2float(kb[(size_t)j * QKVN + d]);
    }
    for (int idx = tid; idx < 100 * (DHEAD / 2); idx += 256) {
        int j = idx >> 5, d2 = idx & 31;
        Vs[j][d2] = (j < SEQ) ? *(const __half2*)(vb + (size_t)j * QKVN + 2 * d2)
                              : __floats2half2_rn(0.f, 0.f);
    }
    if (tid < 8) ps[tid][99] = 0.f;
    __syncthreads();

    for (int si = w; si < SEQ; si += 8) {
        qs[w][lane]      = __half2float(qb[(size_t)si * QKVN + lane]);
        qs[w][lane + 32] = __half2float(qb[(size_t)si * QKVN + lane + 32]);
        __syncwarp();
        float a[4] = {0.f, 0.f, 0.f, 0.f};
#pragma unroll
        for (int d4 = 0; d4 < DHEAD; d4 += 4) {
            float4 qf = *(const float4*)&qs[w][d4];
#pragma unroll
            for (int m = 0; m < 4; m++) {
                int j = lane + m * 32;
                if (j < SEQ) {
                    float4 kf = *(const float4*)&Ks[j][d4];
                    a[m] += qf.x * kf.x + qf.y * kf.y + qf.z * kf.z + qf.w * kf.w;
                }
            }
        }
        float sc[4];
#pragma unroll
        for (int m = 0; m < 4; m++) {
            int j = lane + m * 32;
            sc[m] = (j < SEQ) ? a[m] * 0.125f : -1e30f;
        }
        float mx = fmaxf(fmaxf(sc[0], sc[1]), fmaxf(sc[2], sc[3]));
#pragma unroll
        for (int off = 16; off > 0; off >>= 1) mx = fmaxf(mx, __shfl_xor_sync(0xffffffffu, mx, off));
        float sum = 0.f;
#pragma unroll
        for (int m = 0; m < 4; m++) {
            int j = lane + m * 32;
            float e = (j < SEQ) ? __expf(sc[m] - mx) : 0.f;
            sc[m] = e; sum += e;
        }
#pragma unroll
        for (int off = 16; off > 0; off >>= 1) sum += __shfl_xor_sync(0xffffffffu, sum, off);
        float inv = 1.0f / sum;
#pragma unroll
        for (int m = 0; m < 4; m++) {
            int j = lane + m * 32;
            if (j < SEQ) ps[w][j] = sc[m] * inv;
        }
        __syncwarp();
        float a0 = 0.f, a1 = 0.f;
#pragma unroll
        for (int j4 = 0; j4 < 100; j4 += 4) {
            float4 pv = *(const float4*)&ps[w][j4];
            float2 v0 = __half22float2(Vs[j4 + 0][lane]);
            float2 v1 = __half22float2(Vs[j4 + 1][lane]);
            float2 v2 = __half22float2(Vs[j4 + 2][lane]);
            float2 v3 = __half22float2(Vs[j4 + 3][lane]);
            a0 += pv.x * v0.x + pv.y * v1.x + pv.z * v2.x + pv.w * v3.x;
            a1 += pv.x * v0.y + pv.y * v1.y + pv.z * v2.y + pv.w * v3.y;
        }
        *(__half2*)(ob + (size_t)si * DMODEL + 2 * lane) = __floats2half2_rn(a0, a1);
        __syncwarp();
    }
}

// ======================= launch =======================
extern "C" void kernel_launch(void* const* d_in, const int* in_sizes, int n_in,
                              void* d_out, int out_size) {
    const float* imgs    = (const float*)d_in[0];
    const float* noise   = (const float*)d_in[1];
    const float* patch_w = (const float*)d_in[2];
    const float* patch_b = (const float*)d_in[3];
    const float* pos_emb = (const float*)d_in[4];
    const float* cls_tok = (const float*)d_in[5];
    const float* ln1_s   = (const float*)d_in[6];
    const float* ln1_b   = (const float*)d_in[7];
    const float* wq      = (const float*)d_in[8];
    const float* bq      = (const float*)d_in[9];
    const float* wk      = (const float*)d_in[10];
    const float* bk      = (const float*)d_in[11];
    const float* wv      = (const float*)d_in[12];
    const float* bv      = (const float*)d_in[13];
    const float* wo      = (const float*)d_in[14];
    const float* bo      = (const float*)d_in[15];
    const float* ln2_s   = (const float*)d_in[16];
    const float* ln2_b   = (const float*)d_in[17];
    const float* w1      = (const float*)d_in[18];
    const float* b1      = (const float*)d_in[19];
    const float* w2      = (const float*)d_in[20];
    const float* b2      = (const float*)d_in[21];
    const float* lnf_s   = (const float*)d_in[22];
    const float* lnf_b   = (const float*)d_in[23];

    float* out = (float*)d_out;
    float* out_mask = out + (size_t)NTOK * DMODEL;

    __half *patches, *y, *qkv, *ao, *h1, *pwt, *wqkvt, *wot, *w1t, *w2t;
    float *x0, *x, *bqkv, *gsum, *gssq;
    int* keep;
    cudaGetSymbolAddress((void**)&patches, g_patches);
    cudaGetSymbolAddress((void**)&x0, g_x0);
    cudaGetSymbolAddress((void**)&x,  g_x);
    cudaGetSymbolAddress((void**)&y,  g_y);
    cudaGetSymbolAddress((void**)&qkv, g_qkv);
    cudaGetSymbolAddress((void**)&ao, g_ao);
    cudaGetSymbolAddress((void**)&h1, g_h1);
    cudaGetSymbolAddress((void**)&keep, g_keep);
    cudaGetSymbolAddress((void**)&pwt, g_pwt);
    cudaGetSymbolAddress((void**)&wqkvt, g_wqkvt);
    cudaGetSymbolAddress((void**)&wot, g_wot);
    cudaGetSymbolAddress((void**)&w1t, g_w1t);
    cudaGetSymbolAddress((void**)&w2t, g_w2t);
    cudaGetSymbolAddress((void**)&bqkv, g_bqkv);
    cudaGetSymbolAddress((void**)&gsum, g_sum);
    cudaGetSymbolAddress((void**)&gssq, g_ssq);

    cudaFuncSetAttribute(gemm_h<4, 2, 4>, cudaFuncAttributeMaxDynamicSharedMemorySize, SMEM_A);
    cudaFuncSetAttribute(gemm_h<2, 4, 2>, cudaFuncAttributeMaxDynamicSharedMemorySize, SMEM_B);

    rank_kernel<<<NIMG, 224>>>(noise, keep, out_mask);
    patchify_keep_kernel<<<(NKEPT * PDIM + 255) / 256, 256>>>(imgs, keep, patches);
    zero2_kernel<<<(NSLOT * NTOK + 255) / 256, 256>>>(gsum, gssq);
    wprep_kernel<<<Z_TOT, 256>>>(patch_w, wq, wk, wv, wo, w1, w2, bq, bk, bv,
                                 pwt, wqkvt, wot, w1t, w2t, bqkv);

    // patch embed on kept tokens only: M=3136, N=1024
    {
        dim3 grid(DMODEL / 128, (NKEPT + 127) / 128);
        gemm_h<4, 2, 4><<<grid, 256, SMEM_A>>>(patches, pwt, patch_b, nullptr, x0, nullptr,
                                               NKEPT, DMODEL, PDIM, 0, nullptr, nullptr);
    }
    gather_kernel<<<NTOK, 256>>>(x0, pos_emb, cls_tok, keep, x, gsum, gssq);

    dim3 gQKV(QKVN / 128, (NTOK + 127) / 128);    // 24 x 25 (128-tile)
    dim3 gD64(DMODEL / 128, (NTOK + 63) / 64);    // 8 x 50  (64-tile, 3 CTA/SM)
    dim3 gM(DMLP / 128, (NTOK + 127) / 128);      // 32 x 25 (128-tile)

    for (int i = 0; i < NLAYER; i++) {
        const __half* wqkv_i = wqkvt + (size_t)i * 3 * DMODEL * DMODEL;
        const __half* wo_i = wot + (size_t)i * DMODEL * DMODEL;
        const __half* w1_i = w1t + (size_t)i * DMODEL * DMLP;
        const __half* w2_i = w2t + (size_t)i * DMLP * DMODEL;
        float* s0 = gsum + (size_t)(2 * i) * NTOK;
        float* q0 = gssq + (size_t)(2 * i) * NTOK;
        float* s1 = gsum + (size_t)(2 * i + 1) * NTOK;
        float* q1 = gssq + (size_t)(2 * i + 1) * NTOK;
        float* s2 = gsum + (size_t)(2 * i + 2) * NTOK;
        float* q2 = gssq + (size_t)(2 * i + 2) * NTOK;

        ln_apply<<<NTOK, 128>>>(x, ln1_s + i * DMODEL, ln1_b + i * DMODEL, s0, q0, nullptr, y);
        gemm_h<4, 2, 4><<<gQKV, 256, SMEM_A>>>(y, wqkv_i, bqkv + (size_t)i * QKVN, nullptr,
                                               nullptr, qkv, NTOK, QKVN, DMODEL, 0,
                                               nullptr, nullptr);
        attn_kernel<<<NIMG * NHEAD, 256>>>(qkv, ao);
        gemm_h<2, 4, 2><<<gD64, 256, SMEM_B>>>(ao, wo_i, bo + i * DMODEL, x, x, nullptr,
                                               NTOK, DMODEL, DMODEL, 0, s1, q1);
        ln_apply<<<NTOK, 128>>>(x, ln2_s + i * DMODEL, ln2_b + i * DMODEL, s1, q1, nullptr, y);
        gemm_h<4, 2, 4><<<gM, 256, SMEM_A>>>(y, w1_i, b1 + i * DMLP, nullptr,
                                             nullptr, h1, NTOK, DMLP, DMODEL, 1,
                                             nullptr, nullptr);
        gemm_h<2, 4, 2><<<gD64, 256, SMEM_B>>>(h1, w2_i, b2 + i * DMODEL, x, x, nullptr,
                                               NTOK, DMODEL, DMLP, 0, s2, q2);
    }
    ln_apply<<<NTOK, 128>>>(x, lnf_s, lnf_b, gsum + (size_t)12 * NTOK,
                            gssq + (size_t)12 * NTOK, out, nullptr);
}